// round 1
// baseline (speedup 1.0000x reference)
#include <cuda_runtime.h>
#include <cuda_bf16.h>
#include <cstddef>

// Problem constants
#define Bz   4
#define Hh   8
#define LQ   1024
#define LK   1024
#define DKk  64
#define DVv  64
#define Rr   32
#define R2r  16
#define INV_TEMP (0.125f)

// Scratch (no cudaMalloc allowed)
__device__ float g_Wc[Hh * DKk * DKk];            // combined per-head weight [h][k][d], 128 KB
__device__ float g_P [Bz * Hh * LQ * DKk];        // projected q, [b][h][i][d], 8 MB

// ---------------------------------------------------------------------------
// Kernel 1: W_comb[h] = (W_A @ W_B @ W_Bt @ W_At) * (1/TEMPERATURE)
// W_A:[H,64,32] W_B:[H,32,16] W_Bt:[H,16,32] W_At:[H,32,64]
// ---------------------------------------------------------------------------
__global__ void combine_w_kernel(const float* __restrict__ WA,
                                 const float* __restrict__ WB,
                                 const float* __restrict__ WBt,
                                 const float* __restrict__ WAt) {
    const int h = blockIdx.x;
    __shared__ float sA [64 * 32];
    __shared__ float sB [32 * 16];
    __shared__ float sBt[16 * 32];
    __shared__ float sAt[32 * 64];
    __shared__ float sT1[64 * 16];
    __shared__ float sT2[64 * 32];
    const int t = threadIdx.x;  // 256

    for (int i = t; i < 64 * 32; i += 256) sA [i] = WA [h * 2048 + i];
    for (int i = t; i < 32 * 16; i += 256) sB [i] = WB [h * 512  + i];
    for (int i = t; i < 16 * 32; i += 256) sBt[i] = WBt[h * 512  + i];
    for (int i = t; i < 32 * 64; i += 256) sAt[i] = WAt[h * 2048 + i];
    __syncthreads();

    // T1[64x16] = A[64x32] @ B[32x16]
    for (int i = t; i < 64 * 16; i += 256) {
        int r = i / 16, c = i % 16;
        float s = 0.f;
        #pragma unroll
        for (int k = 0; k < 32; k++) s += sA[r * 32 + k] * sB[k * 16 + c];
        sT1[i] = s;
    }
    __syncthreads();

    // T2[64x32] = T1 @ Bt[16x32]
    for (int i = t; i < 64 * 32; i += 256) {
        int r = i / 32, c = i % 32;
        float s = 0.f;
        #pragma unroll
        for (int k = 0; k < 16; k++) s += sT1[r * 16 + k] * sBt[k * 32 + c];
        sT2[i] = s;
    }
    __syncthreads();

    // Wc[64x64] = T2 @ At[32x64], scaled
    for (int i = t; i < 64 * 64; i += 256) {
        int r = i / 64, c = i % 64;
        float s = 0.f;
        #pragma unroll
        for (int k = 0; k < 32; k++) s += sT2[r * 32 + k] * sAt[k * 64 + c];
        g_Wc[h * 4096 + i] = s * INV_TEMP;
    }
}

// ---------------------------------------------------------------------------
// Kernel 2: P[b][h][i][d] = sum_k q[b][i][h][k] * Wc[h][k][d]
// grid = B*H*16 (64-row tiles), 256 threads
// ---------------------------------------------------------------------------
__global__ void __launch_bounds__(256) project_kernel(const float* __restrict__ q) {
    const int bid = blockIdx.x;
    const int it  = bid & 15;
    const int h   = (bid >> 4) & 7;
    const int b   = bid >> 7;

    __shared__ float sW[64 * 64];
    __shared__ float sQ[64 * 65];
    const int t = threadIdx.x;

    for (int i = t; i < 4096; i += 256) sW[i] = g_Wc[h * 4096 + i];
    for (int i = t; i < 4096; i += 256) {
        int r = i >> 6, k = i & 63;
        sQ[r * 65 + k] = q[((size_t)(b * LQ + it * 64 + r) * Hh + h) * DKk + k];
    }
    __syncthreads();

    const int c  = t & 63;
    const int rg = t >> 6;            // 0..3
    float acc[16];
    #pragma unroll
    for (int j = 0; j < 16; j++) acc[j] = 0.f;

    #pragma unroll 4
    for (int k = 0; k < 64; k++) {
        float w = sW[k * 64 + c];
        #pragma unroll
        for (int j = 0; j < 16; j++) acc[j] += sQ[(rg + 4 * j) * 65 + k] * w;
    }
    #pragma unroll
    for (int j = 0; j < 16; j++) {
        int r = it * 64 + rg + 4 * j;
        g_P[(((size_t)b * Hh + h) * LQ + r) * DKk + c] = acc[j];
    }
}

// ---------------------------------------------------------------------------
// Kernel 3: fused  S = P @ qt ; softmax ; attn out ; O = A @ v
// One block per (b, h, 32-row tile). 256 threads = 8 warps; warp tr owns rows
// tr*4 .. tr*4+3 through ALL phases (no cross-warp deps except tile buffer).
// smem: sS[32][1024] | tile buf (qt 64x132 / v 128x68) | sP[32][64]
// ---------------------------------------------------------------------------
#define SM_S_FLOATS   (32 * 1024)
#define SM_T_FLOATS   (128 * 68)        // >= 64*132 (8448) -> 8704
#define SM_P_FLOATS   (32 * 64)
#define SMEM_C_BYTES  ((SM_S_FLOATS + SM_T_FLOATS + SM_P_FLOATS) * 4)

__global__ void __launch_bounds__(256) attn_kernel(const float* __restrict__ qt,
                                                   const float* __restrict__ v,
                                                   float* __restrict__ attn,
                                                   float* __restrict__ outp) {
    extern __shared__ float smem[];
    float* sS = smem;                          // [32][1024]
    float* sT = smem + SM_S_FLOATS;            // tile buffer
    float* sP = smem + SM_S_FLOATS + SM_T_FLOATS;  // [32][64]

    const int bid = blockIdx.x;
    const int it  = bid & 31;
    const int h   = (bid >> 5) & 7;
    const int b   = bid >> 8;
    const int i0  = it * 32;

    const int t  = threadIdx.x;
    const int tr = t >> 5;     // warp id 0..7 -> rows tr*4..tr*4+3
    const int tc = t & 31;     // lane

    const float* qtp = qt + ((size_t)(b * Hh + h) * DKk) * LK;        // [64][1024]
    const float* vp  = v  + ((size_t)(b * Hh + h) * LK) * DVv;        // [1024][64]

    // load P rows for this tile: [32][64]
    for (int i = t; i < 32 * 64; i += 256) {
        int r = i >> 6, k = i & 63;
        sP[r * 64 + k] = g_P[(((size_t)b * Hh + h) * LQ + i0 + r) * DKk + k];
    }

    // ---------------- Phase A: S[32][1024] = P @ qt ----------------
    for (int jt = 0; jt < LK; jt += 128) {
        __syncthreads();
        // load qt tile [64 k][128 j] into sT (stride 132)
        for (int i = t; i < (64 * 128) / 4; i += 256) {
            int k  = i >> 5;
            int jj = (i & 31) * 4;
            float4 val = *(const float4*)&qtp[(size_t)k * LK + jt + jj];
            *(float4*)&sT[k * 132 + jj] = val;
        }
        __syncthreads();

        float acc[4][4];
        #pragma unroll
        for (int u = 0; u < 4; u++)
            #pragma unroll
            for (int w = 0; w < 4; w++) acc[u][w] = 0.f;

        const float* p0 = &sP[(tr * 4 + 0) * 64];
        const float* p1 = &sP[(tr * 4 + 1) * 64];
        const float* p2 = &sP[(tr * 4 + 2) * 64];
        const float* p3 = &sP[(tr * 4 + 3) * 64];

        #pragma unroll 4
        for (int k = 0; k < 64; k++) {
            float4 bq = *(const float4*)&sT[k * 132 + tc * 4];
            float a0 = p0[k], a1 = p1[k], a2 = p2[k], a3 = p3[k];
            acc[0][0] += a0 * bq.x; acc[0][1] += a0 * bq.y; acc[0][2] += a0 * bq.z; acc[0][3] += a0 * bq.w;
            acc[1][0] += a1 * bq.x; acc[1][1] += a1 * bq.y; acc[1][2] += a1 * bq.z; acc[1][3] += a1 * bq.w;
            acc[2][0] += a2 * bq.x; acc[2][1] += a2 * bq.y; acc[2][2] += a2 * bq.z; acc[2][3] += a2 * bq.w;
            acc[3][0] += a3 * bq.x; acc[3][1] += a3 * bq.y; acc[3][2] += a3 * bq.z; acc[3][3] += a3 * bq.w;
        }
        #pragma unroll
        for (int u = 0; u < 4; u++) {
            *(float4*)&sS[(tr * 4 + u) * 1024 + jt + tc * 4] =
                make_float4(acc[u][0], acc[u][1], acc[u][2], acc[u][3]);
        }
    }

    // ---------------- Phase B: softmax per row + write attn ----------------
    // warp tr owns rows tr*4..tr*4+3 (it wrote them; no barrier needed for sS)
    #pragma unroll
    for (int u = 0; u < 4; u++) {
        const int r = tr * 4 + u;
        float* Srow = &sS[r * 1024];
        float m = -1e30f;
        for (int j = tc * 4; j < 1024; j += 128) {
            float4 x = *(const float4*)&Srow[j];
            m = fmaxf(m, fmaxf(fmaxf(x.x, x.y), fmaxf(x.z, x.w)));
        }
        #pragma unroll
        for (int o = 16; o; o >>= 1) m = fmaxf(m, __shfl_xor_sync(0xffffffffu, m, o));

        float s = 0.f;
        for (int j = tc * 4; j < 1024; j += 128) {
            float4 x = *(const float4*)&Srow[j];
            x.x = __expf(x.x - m); x.y = __expf(x.y - m);
            x.z = __expf(x.z - m); x.w = __expf(x.w - m);
            *(float4*)&Srow[j] = x;
            s += x.x + x.y + x.z + x.w;
        }
        #pragma unroll
        for (int o = 16; o; o >>= 1) s += __shfl_xor_sync(0xffffffffu, s, o);
        const float inv = 1.0f / s;

        float* arow = attn + (((size_t)(b * Hh + h) * LQ + i0 + r)) * (size_t)LK;
        for (int j = tc * 4; j < 1024; j += 128) {
            float4 x = *(const float4*)&Srow[j];
            x.x *= inv; x.y *= inv; x.z *= inv; x.w *= inv;
            *(float4*)&Srow[j] = x;
            *(float4*)&arow[j] = x;
        }
    }

    // ---------------- Phase C: O[32][64] = A @ v ----------------
    const int cc = tc * 2;   // column pair
    float oac[4][2];
    #pragma unroll
    for (int u = 0; u < 4; u++) { oac[u][0] = 0.f; oac[u][1] = 0.f; }

    for (int kt = 0; kt < LK; kt += 128) {
        __syncthreads();
        // load v tile [128 k][64 c] into sT (stride 68)
        for (int i = t; i < (128 * 64) / 4; i += 256) {
            int k = i >> 4;
            int c = (i & 15) * 4;
            float4 val = *(const float4*)&vp[(size_t)(kt + k) * DVv + c];
            *(float4*)&sT[k * 68 + c] = val;
        }
        __syncthreads();

        const float* A0 = &sS[(tr * 4 + 0) * 1024 + kt];
        const float* A1 = &sS[(tr * 4 + 1) * 1024 + kt];
        const float* A2 = &sS[(tr * 4 + 2) * 1024 + kt];
        const float* A3 = &sS[(tr * 4 + 3) * 1024 + kt];

        #pragma unroll 4
        for (int k = 0; k < 128; k++) {
            float2 bv = *(const float2*)&sT[k * 68 + cc];
            float a0 = A0[k], a1 = A1[k], a2 = A2[k], a3 = A3[k];
            oac[0][0] += a0 * bv.x; oac[0][1] += a0 * bv.y;
            oac[1][0] += a1 * bv.x; oac[1][1] += a1 * bv.y;
            oac[2][0] += a2 * bv.x; oac[2][1] += a2 * bv.y;
            oac[3][0] += a3 * bv.x; oac[3][1] += a3 * bv.y;
        }
    }
    #pragma unroll
    for (int u = 0; u < 4; u++) {
        const int r = tr * 4 + u;
        float* orow = outp + (((size_t)(b * Hh + h) * LQ + i0 + r)) * DVv;
        *(float2*)&orow[cc] = make_float2(oac[u][0], oac[u][1]);
    }
}

// ---------------------------------------------------------------------------
// Launch: inputs (metadata order): q, W_A, W_B, W_At, W_Bt, qt, v, d_k, mask
// Output assumed concat [output(2,097,152 fp32), attn(33,554,432 fp32)]
// ---------------------------------------------------------------------------
extern "C" void kernel_launch(void* const* d_in, const int* in_sizes, int n_in,
                              void* d_out, int out_size) {
    const float* q   = (const float*)d_in[0];
    const float* WA  = (const float*)d_in[1];
    const float* WB  = (const float*)d_in[2];
    const float* WAt = (const float*)d_in[3];
    const float* WBt = (const float*)d_in[4];
    const float* qt  = (const float*)d_in[5];
    const float* v   = (const float*)d_in[6];

    float* outp = (float*)d_out;
    const size_t attn_elems = (size_t)Bz * Hh * LQ * LK;   // 33,554,432
    float* attn = outp + ((size_t)out_size - attn_elems);  // concat layout

    cudaFuncSetAttribute(attn_kernel, cudaFuncAttributeMaxDynamicSharedMemorySize,
                         SMEM_C_BYTES);

    combine_w_kernel<<<Hh, 256>>>(WA, WB, WBt, WAt);
    project_kernel<<<Bz * Hh * 16, 256>>>(q);
    attn_kernel<<<Bz * Hh * 32, 256, SMEM_C_BYTES>>>(qt, v, attn, outp);
}

// round 3
// speedup vs baseline: 1.0465x; 1.0465x over previous
#include <cuda_runtime.h>
#include <cuda_bf16.h>
#include <cstdint>
#include <cstddef>

#define Bz   4
#define Hh   8
#define LQ   1024
#define LK   1024
#define DKk  64
#define DVv  64

__device__ float g_Wc[Hh * 64 * 64];
__device__ float g_P [Bz * Hh * LQ * 64];

// ===================== helpers =====================
__device__ __forceinline__ uint32_t packbf(float lo, float hi) {
    // returns bf16x2 {low16 = bf16(lo), high16 = bf16(hi)}
    uint32_t r;
    asm("cvt.rn.bf16x2.f32 %0, %1, %2;" : "=r"(r) : "f"(hi), "f"(lo));
    return r;
}
__device__ __forceinline__ float lo_of(float x) {
    return x - __bfloat162float(__float2bfloat16(x));
}
__device__ __forceinline__ void mma16816(float* c,
                                         uint32_t a0, uint32_t a1, uint32_t a2, uint32_t a3,
                                         uint32_t b0, uint32_t b1) {
    asm volatile(
        "mma.sync.aligned.m16n8k16.row.col.f32.bf16.bf16.f32 "
        "{%0,%1,%2,%3}, {%4,%5,%6,%7}, {%8,%9}, {%0,%1,%2,%3};"
        : "+f"(c[0]), "+f"(c[1]), "+f"(c[2]), "+f"(c[3])
        : "r"(a0), "r"(a1), "r"(a2), "r"(a3), "r"(b0), "r"(b1));
}

// ===================== Kernel 1: weight combine =====================
__global__ void __launch_bounds__(128) combine_w_kernel(const float* __restrict__ WA,
                                                        const float* __restrict__ WB,
                                                        const float* __restrict__ WBt,
                                                        const float* __restrict__ WAt) {
    const int h  = blockIdx.x >> 3;
    const int r0 = (blockIdx.x & 7) * 8;
    __shared__ float sA[8 * 32], sB[32 * 16], sBt[16 * 32], sAt[32 * 64];
    __shared__ float sT1[8 * 16], sT2[8 * 32];
    const int t = threadIdx.x;

    for (int i = t; i < 8 * 32; i += 128) sA[i] = WA[h * 2048 + (r0 + i / 32) * 32 + (i % 32)];
    for (int i = t; i < 512; i += 128) sB[i]  = WB [h * 512 + i];
    for (int i = t; i < 512; i += 128) sBt[i] = WBt[h * 512 + i];
    for (int i = t; i < 2048; i += 128) sAt[i] = WAt[h * 2048 + i];
    __syncthreads();

    {
        int r = t / 16, c = t % 16;
        float s = 0.f;
        #pragma unroll
        for (int k = 0; k < 32; k++) s += sA[r * 32 + k] * sB[k * 16 + c];
        sT1[t] = s;
    }
    __syncthreads();
    for (int i = t; i < 256; i += 128) {
        int r = i / 32, c = i % 32;
        float s = 0.f;
        #pragma unroll
        for (int k = 0; k < 16; k++) s += sT1[r * 16 + k] * sBt[k * 32 + c];
        sT2[i] = s;
    }
    __syncthreads();
    for (int i = t; i < 512; i += 128) {
        int r = i / 64, c = i % 64;
        float s = 0.f;
        #pragma unroll
        for (int k = 0; k < 32; k++) s += sT2[r * 32 + k] * sAt[k * 64 + c];
        g_Wc[h * 4096 + (r0 + r) * 64 + c] = s * 0.125f;
    }
}

// ===================== Kernel 2: P = q @ Wc =====================
__global__ void __launch_bounds__(256) project_kernel(const float* __restrict__ q) {
    const int bid = blockIdx.x;
    const int it  = bid & 15;
    const int h   = (bid >> 4) & 7;
    const int b   = bid >> 7;

    __shared__ float sW[64 * 64];
    __shared__ float sQ[64 * 65];
    const int t = threadIdx.x;

    for (int i = t; i < 4096; i += 256) sW[i] = g_Wc[h * 4096 + i];
    for (int i = t; i < 4096; i += 256) {
        int r = i >> 6, k = i & 63;
        sQ[r * 65 + k] = q[((size_t)(b * LQ + it * 64 + r) * Hh + h) * DKk + k];
    }
    __syncthreads();

    const int c  = t & 63;
    const int rg = t >> 6;
    float acc[16];
    #pragma unroll
    for (int j = 0; j < 16; j++) acc[j] = 0.f;

    #pragma unroll 4
    for (int k = 0; k < 64; k++) {
        float w = sW[k * 64 + c];
        #pragma unroll
        for (int j = 0; j < 16; j++) acc[j] += sQ[(rg + 4 * j) * 65 + k] * w;
    }
    #pragma unroll
    for (int j = 0; j < 16; j++) {
        int r = it * 64 + rg + 4 * j;
        g_P[(((size_t)b * Hh + h) * LQ + r) * DKk + c] = acc[j];
    }
}

// ===================== Kernel 3: warp-MMA flash attention =====================
// smem (uint32 words): QTH[128*36] QTL[128*36] VTH[64*68] VTL[64*68]
#define QTH_OFF 0
#define QTL_OFF 4608
#define VTH_OFF 9216
#define VTL_OFF 13568
#define SMEM_WORDS 17920
#define SMEM_BYTES (SMEM_WORDS * 4)

__global__ void __launch_bounds__(256, 1) attn_kernel(const float* __restrict__ qt,
                                                      const float* __restrict__ v,
                                                      float* __restrict__ attn,
                                                      float* __restrict__ outp) {
    extern __shared__ uint32_t smw[];
    uint32_t* QTH = smw + QTH_OFF;
    uint32_t* QTL = smw + QTL_OFF;
    uint32_t* VTH = smw + VTH_OFF;
    uint32_t* VTL = smw + VTL_OFF;

    const int bid = blockIdx.x;
    const int mt  = bid & 7;
    const int h   = (bid >> 3) & 7;
    const int b   = bid >> 6;
    const int i0  = mt * 128;

    const int t    = threadIdx.x;
    const int w    = t >> 5;
    const int lane = t & 31;
    const int grp  = lane >> 2;   // row within 8-group
    const int q4   = lane & 3;    // col quad

    const float* qtp = qt + ((size_t)(b * Hh + h) * DKk) * LK;   // [64][1024]
    const float* vp  = v  + ((size_t)(b * Hh + h) * LK) * DVv;   // [1024][64]
    float* attn_base = attn + ((size_t)(b * Hh + h) * LQ + i0) * (size_t)LK;
    float* out_base  = outp + ((size_t)(b * Hh + h) * LQ + i0) * (size_t)DVv;

    // ---- persistent A fragments of P (hi/lo), warp rows w*16 .. w*16+15 ----
    const int rA = w * 16 + grp;
    const int rB = rA + 8;
    uint32_t pah[4][4], pal[4][4];
    {
        const float* Pp = g_P + ((size_t)(b * Hh + h) * LQ + i0) * DKk;
        #pragma unroll
        for (int kt = 0; kt < 4; kt++) {
            int k = kt * 16 + 2 * q4;
            float x0 = Pp[rA * 64 + k],     x1 = Pp[rA * 64 + k + 1];
            float y0 = Pp[rB * 64 + k],     y1 = Pp[rB * 64 + k + 1];
            float x8 = Pp[rA * 64 + k + 8], x9 = Pp[rA * 64 + k + 9];
            float y8 = Pp[rB * 64 + k + 8], y9 = Pp[rB * 64 + k + 9];
            pah[kt][0] = packbf(x0, x1); pah[kt][1] = packbf(y0, y1);
            pah[kt][2] = packbf(x8, x9); pah[kt][3] = packbf(y8, y9);
            pal[kt][0] = packbf(lo_of(x0), lo_of(x1));
            pal[kt][1] = packbf(lo_of(y0), lo_of(y1));
            pal[kt][2] = packbf(lo_of(x8), lo_of(x9));
            pal[kt][3] = packbf(lo_of(y8), lo_of(y9));
        }
    }

    float m0 = -1e30f, m1 = -1e30f, s0 = 0.f, s1 = 0.f;

    // ================= PASS A: online (max,sum), hi-only MMA =================
    #pragma unroll 1
    for (int ch = 0; ch < 8; ch++) {
        const int j0 = ch * 128;
        __syncthreads();
        #pragma unroll 1
        for (int i = 0; i < 16; i++) {        // qtT hi: 4096 bf16x2
            int idx = t + 256 * i;
            int j = idx & 127, kp = idx >> 7;
            float f0 = qtp[(size_t)(2 * kp) * LK + j0 + j];
            float f1 = qtp[(size_t)(2 * kp + 1) * LK + j0 + j];
            QTH[j * 36 + kp] = packbf(f0, f1);
        }
        __syncthreads();

        float acc[16][4];
        #pragma unroll
        for (int nt = 0; nt < 16; nt++) {
            #pragma unroll
            for (int u = 0; u < 4; u++) acc[nt][u] = 0.f;
            const uint32_t* Brow = QTH + (8 * nt + grp) * 36 + q4;
            #pragma unroll
            for (int kt = 0; kt < 4; kt++)
                mma16816(acc[nt], pah[kt][0], pah[kt][1], pah[kt][2], pah[kt][3],
                         Brow[8 * kt], Brow[8 * kt + 4]);
        }
        // online update
        float cm0 = -1e30f, cm1 = -1e30f;
        #pragma unroll
        for (int nt = 0; nt < 16; nt++) {
            cm0 = fmaxf(cm0, fmaxf(acc[nt][0], acc[nt][1]));
            cm1 = fmaxf(cm1, fmaxf(acc[nt][2], acc[nt][3]));
        }
        cm0 = fmaxf(cm0, __shfl_xor_sync(0xffffffffu, cm0, 1));
        cm0 = fmaxf(cm0, __shfl_xor_sync(0xffffffffu, cm0, 2));
        cm1 = fmaxf(cm1, __shfl_xor_sync(0xffffffffu, cm1, 1));
        cm1 = fmaxf(cm1, __shfl_xor_sync(0xffffffffu, cm1, 2));
        float nm0 = fmaxf(m0, cm0), nm1 = fmaxf(m1, cm1);
        float sn0 = 0.f, sn1 = 0.f;
        #pragma unroll
        for (int nt = 0; nt < 16; nt++) {
            sn0 += __expf(acc[nt][0] - nm0) + __expf(acc[nt][1] - nm0);
            sn1 += __expf(acc[nt][2] - nm1) + __expf(acc[nt][3] - nm1);
        }
        sn0 += __shfl_xor_sync(0xffffffffu, sn0, 1);
        sn0 += __shfl_xor_sync(0xffffffffu, sn0, 2);
        sn1 += __shfl_xor_sync(0xffffffffu, sn1, 1);
        sn1 += __shfl_xor_sync(0xffffffffu, sn1, 2);
        s0 = s0 * __expf(m0 - nm0) + sn0;  m0 = nm0;
        s1 = s1 * __expf(m1 - nm1) + sn1;  m1 = nm1;
    }
    const float is0 = 1.f / s0;
    const float is1 = 1.f / s1;

    // ================= PASS B: 3-term S, attn out, O += E@V =================
    float oacc[8][4];
    #pragma unroll
    for (int nt = 0; nt < 8; nt++)
        #pragma unroll
        for (int u = 0; u < 4; u++) oacc[nt][u] = 0.f;

    #pragma unroll 1
    for (int ch = 0; ch < 8; ch++) {
        const int j0 = ch * 128;
        __syncthreads();
        #pragma unroll 1
        for (int i = 0; i < 16; i++) {        // qtT hi+lo
            int idx = t + 256 * i;
            int j = idx & 127, kp = idx >> 7;
            float f0 = qtp[(size_t)(2 * kp) * LK + j0 + j];
            float f1 = qtp[(size_t)(2 * kp + 1) * LK + j0 + j];
            QTH[j * 36 + kp] = packbf(f0, f1);
            QTL[j * 36 + kp] = packbf(lo_of(f0), lo_of(f1));
        }
        #pragma unroll 1
        for (int i = 0; i < 16; i++) {        // VT hi+lo
            int idx = t + 256 * i;
            int n = idx & 63, jp = idx >> 6;
            float f0 = vp[(size_t)(j0 + 2 * jp) * DVv + n];
            float f1 = vp[(size_t)(j0 + 2 * jp + 1) * DVv + n];
            VTH[n * 68 + jp] = packbf(f0, f1);
            VTL[n * 68 + jp] = packbf(lo_of(f0), lo_of(f1));
        }
        __syncthreads();

        float acc[16][4];
        #pragma unroll
        for (int nt = 0; nt < 16; nt++) {
            #pragma unroll
            for (int u = 0; u < 4; u++) acc[nt][u] = 0.f;
            const uint32_t* Bh = QTH + (8 * nt + grp) * 36 + q4;
            const uint32_t* Bl = QTL + (8 * nt + grp) * 36 + q4;
            #pragma unroll
            for (int kt = 0; kt < 4; kt++) {
                uint32_t bh0 = Bh[8 * kt], bh1 = Bh[8 * kt + 4];
                uint32_t bl0 = Bl[8 * kt], bl1 = Bl[8 * kt + 4];
                mma16816(acc[nt], pah[kt][0], pah[kt][1], pah[kt][2], pah[kt][3], bh0, bh1);
                mma16816(acc[nt], pah[kt][0], pah[kt][1], pah[kt][2], pah[kt][3], bl0, bl1);
                mma16816(acc[nt], pal[kt][0], pal[kt][1], pal[kt][2], pal[kt][3], bh0, bh1);
            }
        }

        // exp + attn store + O-MMA (C-frag of S reused as A-frag of O)
        #pragma unroll
        for (int kt = 0; kt < 8; kt++) {
            const int t0 = 2 * kt, t1 = 2 * kt + 1;
            float e00 = __expf(acc[t0][0] - m0) * is0;
            float e01 = __expf(acc[t0][1] - m0) * is0;
            float e02 = __expf(acc[t0][2] - m1) * is1;
            float e03 = __expf(acc[t0][3] - m1) * is1;
            float e10 = __expf(acc[t1][0] - m0) * is0;
            float e11 = __expf(acc[t1][1] - m0) * is0;
            float e12 = __expf(acc[t1][2] - m1) * is1;
            float e13 = __expf(acc[t1][3] - m1) * is1;

            *(float2*)&attn_base[(size_t)rA * LK + j0 + 8 * t0 + 2 * q4] = make_float2(e00, e01);
            *(float2*)&attn_base[(size_t)rB * LK + j0 + 8 * t0 + 2 * q4] = make_float2(e02, e03);
            *(float2*)&attn_base[(size_t)rA * LK + j0 + 8 * t1 + 2 * q4] = make_float2(e10, e11);
            *(float2*)&attn_base[(size_t)rB * LK + j0 + 8 * t1 + 2 * q4] = make_float2(e12, e13);

            uint32_t eh0 = packbf(e00, e01), eh1 = packbf(e02, e03);
            uint32_t eh2 = packbf(e10, e11), eh3 = packbf(e12, e13);
            uint32_t el0 = packbf(lo_of(e00), lo_of(e01));
            uint32_t el1 = packbf(lo_of(e02), lo_of(e03));
            uint32_t el2 = packbf(lo_of(e10), lo_of(e11));
            uint32_t el3 = packbf(lo_of(e12), lo_of(e13));

            #pragma unroll
            for (int nt = 0; nt < 8; nt++) {
                const uint32_t* Vh = VTH + (8 * nt + grp) * 68 + q4;
                const uint32_t* Vl = VTL + (8 * nt + grp) * 68 + q4;
                uint32_t vh0 = Vh[8 * kt], vh1 = Vh[8 * kt + 4];
                uint32_t vl0 = Vl[8 * kt], vl1 = Vl[8 * kt + 4];
                mma16816(oacc[nt], eh0, eh1, eh2, eh3, vh0, vh1);
                mma16816(oacc[nt], eh0, eh1, eh2, eh3, vl0, vl1);
                mma16816(oacc[nt], el0, el1, el2, el3, vh0, vh1);
            }
        }
    }

    // ================= epilogue: O store =================
    #pragma unroll
    for (int nt = 0; nt < 8; nt++) {
        *(float2*)&out_base[(size_t)rA * DVv + 8 * nt + 2 * q4] =
            make_float2(oacc[nt][0], oacc[nt][1]);
        *(float2*)&out_base[(size_t)rB * DVv + 8 * nt + 2 * q4] =
            make_float2(oacc[nt][2], oacc[nt][3]);
    }
}

// ===================== launch =====================
extern "C" void kernel_launch(void* const* d_in, const int* in_sizes, int n_in,
                              void* d_out, int out_size) {
    const float* q   = (const float*)d_in[0];
    const float* WA  = (const float*)d_in[1];
    const float* WB  = (const float*)d_in[2];
    const float* WAt = (const float*)d_in[3];
    const float* WBt = (const float*)d_in[4];
    const float* qt  = (const float*)d_in[5];
    const float* v   = (const float*)d_in[6];

    float* outp = (float*)d_out;
    const size_t attn_elems = (size_t)Bz * Hh * LQ * LK;
    float* attn = outp + ((size_t)out_size - attn_elems);

    cudaFuncSetAttribute(attn_kernel, cudaFuncAttributeMaxDynamicSharedMemorySize,
                         SMEM_BYTES);

    combine_w_kernel<<<64, 128>>>(WA, WB, WBt, WAt);
    project_kernel<<<Bz * Hh * 16, 256>>>(q);
    attn_kernel<<<Bz * Hh * 8, 256, SMEM_BYTES>>>(qt, v, attn, outp);
}